// round 14
// baseline (speedup 1.0000x reference)
#include <cuda_runtime.h>
#include <cuda_bf16.h>
#include <cstddef>
#include <cstdint>

// Problem constants (fixed by the dataset)
#define BATCH 64
#define LSEQ  512
#define DIN   256
#define HDIM  256
#define H3    768
#define ADIM  128
#define DEPTH 4
#define NROWS (LSEQ * BATCH)   // 32768

// ---- scan: 4-CTA clusters, 2 batches per cluster, col-aligned weight rows ----
#define C4_NCTAS   4
#define R4         192         // weight rows per CTA (3 blocks of 64)
#define NB4        2           // batches per cluster
#define NCLU4      32
#define SCAN_THREADS 896
#define WROW4_F4   65          // 64 data f4 + 1 pad
#define G4_REC     136         // floats per rank record: 4 stats + 128 h + pad
#define CLUBUF4    (C4_NCTAS * G4_REC)   // 544 floats per parity
#define SL_STRIDE  520

// hT layout (2 batches): 4 k-blocks of 33 f4 (32 data + 1 pad)
#define HT2_FLT(c, b) ((((((c) >> 6) * 33) + (((c) & 63) >> 1)) << 2) + (((c) & 1) * 2) + (b))

// ---------------- scratch (device globals; no allocation allowed) -------------
__device__ float g_h0  [(size_t)NROWS * HDIM];
__device__ float g_h1  [(size_t)NROWS * HDIM];
__device__ float g_xpc [(size_t)(NROWS + 64) * H3];  // compacted xp
__device__ float g_xa  [(size_t)NROWS * ADIM];
__device__ float g_Ut  [(size_t)H3 * HDIM];          // U^T (768x256)
__device__ float g_hp  [(size_t)NCLU4 * 2 * CLUBUF4];
__device__ int   g_steplist[BATCH * SL_STRIDE];
__device__ int   g_nsteps[BATCH];
__device__ int   g_off  [BATCH + 1];
__device__ int   g_rowA [NROWS + 64];
__device__ int   g_srcE [NROWS];
__device__ int   g_srcI [2][NROWS];
__device__ int   g_mtotal;
__device__ unsigned char g_mask[BATCH * LSEQ];

// ---------------------------------- helpers ----------------------------------
__device__ __forceinline__ float warp_sum(float v) {
#pragma unroll
    for (int o = 16; o > 0; o >>= 1) v += __shfl_down_sync(0xffffffffu, v, o);
    return v;
}
__device__ __forceinline__ float fsig(float x) {
    float e = __expf(-x);
    return __fdividef(1.0f, 1.0f + e);
}
__device__ __forceinline__ float ftanhf(float x) {
    float e = __expf(2.0f * x);
    return 1.0f - __fdividef(2.0f, e + 1.0f);
}
__device__ __forceinline__ void fma2(unsigned long long& d, unsigned long long a,
                                     unsigned long long b) {
    asm("fma.rn.f32x2 %0, %1, %2, %0;" : "+l"(d) : "l"(a), "l"(b));
}
__device__ __forceinline__ unsigned long long pk(float lo, float hi) {
    unsigned long long r;
    asm("mov.b64 %0, {%1, %2};" : "=l"(r) : "f"(lo), "f"(hi));
    return r;
}
__device__ __forceinline__ float2 upk(unsigned long long v) {
    float2 r;
    asm("mov.b64 {%0, %1}, %2;" : "=f"(r.x), "=f"(r.y) : "l"(v));
    return r;
}

// ------------- per-batch plan body (lists, offsets, rowA, srcE, srcI) ---------
__device__ __forceinline__ void plan_batch(const unsigned char* m, int b, int ibuf) {
    int n = 0, src = -1;
    for (int l = 0; l < LSEQ; l++) {
        int prev = src;
        if (m[l]) { g_steplist[b * SL_STRIDE + n] = l; n++; src = l; }
        int r = l * BATCH + b;
        g_srcE[r]       = (prev < 0) ? -1 : prev * BATCH + b;
        g_srcI[ibuf][r] = (src  < 0) ? -1 : src  * BATCH + b;
    }
    g_nsteps[b] = n;
    for (int i = n; i <= LSEQ; i++) g_steplist[b * SL_STRIDE + i] = -1;
}

// ----------------- prep: U transpose + mask copy + depth-0 plan ---------------
__global__ void prep_fused(const float* __restrict__ U,
                           const unsigned char* __restrict__ m8) {
    int k = blockIdx.x;
    if (k < H3) {
        int i = threadIdx.x;
        g_Ut[(size_t)k * HDIM + i] = U[(size_t)i * H3 + k];
        return;
    }
    __shared__ unsigned char smm[BATCH * LSEQ];
    __shared__ int mode;
    int t = threadIdx.x;
    if (t == 0) {
        int nz = 0;
        for (int i = 0; i < 64; i++) nz |= m8[4 * i + 1] | m8[4 * i + 2] | m8[4 * i + 3];
        mode = nz ? 1 : 0;
    }
    __syncthreads();
    if (mode) {
        for (int i = t; i < BATCH * LSEQ; i += blockDim.x) {
            unsigned char v = m8[i] ? 1 : 0;
            g_mask[i] = v; smm[i] = v;
        }
    } else {
        const int* m32 = (const int*)m8;
        for (int i = t; i < BATCH * LSEQ; i += blockDim.x) {
            unsigned char v = m32[i] ? 1 : 0;
            g_mask[i] = v; smm[i] = v;
        }
    }
    __syncthreads();
    if (t < BATCH) plan_batch(smm + t * LSEQ, t, 0);
    __syncthreads();
    if (t == 0) {
        int acc = 0;
        for (int b = 0; b < BATCH; b++) { g_off[b] = acc; acc += g_nsteps[b]; }
        g_off[BATCH] = acc;
        g_mtotal = acc;
    }
    __syncthreads();
    if (t < BATCH) {
        int b = t, off = g_off[b], n = g_nsteps[b];
        for (int i = 0; i < n; i++)
            g_rowA[off + i] = g_steplist[b * SL_STRIDE + i] * BATCH + b;
    }
}

// ---------------- plan (d>=1): one block, everything ---------------------------
__global__ void plan_kernel(int ibuf) {
    __shared__ unsigned char smm[BATCH * LSEQ];
    int t = threadIdx.x;   // 1024
    for (int i = t; i < BATCH * LSEQ; i += blockDim.x) smm[i] = g_mask[i];
    __syncthreads();
    if (t < BATCH) plan_batch(smm + t * LSEQ, t, ibuf);
    __syncthreads();
    if (t == 0) {
        int acc = 0;
        for (int b = 0; b < BATCH; b++) { g_off[b] = acc; acc += g_nsteps[b]; }
        g_off[BATCH] = acc;
        g_mtotal = acc;
    }
    __syncthreads();
    if (t < BATCH) {
        int b = t, off = g_off[b], n = g_nsteps[b];
        for (int i = 0; i < n; i++)
            g_rowA[off + i] = g_steplist[b * SL_STRIDE + i] * BATCH + b;
    }
}

// ------------------------------- tiled SGEMM (f32x2) --------------------------
template <int MODE>
__global__ void __launch_bounds__(256) sgemm_kernel(
    const float* __restrict__ A, const float* __restrict__ Bm,
    const float* __restrict__ bias, float* __restrict__ C, int N) {
    const int K = 256;
    __shared__ __align__(16) float Ast[16][68];
    __shared__ __align__(16) float Bs[16][64];
    int t  = threadIdx.x;
    int m0 = blockIdx.y * 64;
    int n0 = blockIdx.x * 64;
    if (MODE == 3 && m0 >= g_mtotal) return;
    int ty = t >> 4, tx = t & 15;

    unsigned long long acc2[4][2];
#pragma unroll
    for (int i = 0; i < 4; i++) { acc2[i][0] = 0ull; acc2[i][1] = 0ull; }

    int ar = t >> 2;
    int ak = (t & 3) * 4;
    int arow = m0 + ar;
    const float* Aptr;
    if (MODE == 1) {
        int b = arow & 63, l = arow >> 6;
        Aptr = A + ((size_t)b * LSEQ + l) * K;
    } else {
        int mt = g_mtotal;
        int rr = (arow < mt) ? arow : (mt - 1);
        Aptr = A + (size_t)g_rowA[rr] * K;
    }
    int bk = t >> 4;
    int bn = (t & 15) * 4;

    for (int k0 = 0; k0 < K; k0 += 16) {
        float4 av = *(const float4*)(Aptr + k0 + ak);
        Ast[ak + 0][ar] = av.x;
        Ast[ak + 1][ar] = av.y;
        Ast[ak + 2][ar] = av.z;
        Ast[ak + 3][ar] = av.w;
        *(float4*)(&Bs[bk][bn]) = *(const float4*)(Bm + (size_t)(k0 + bk) * N + n0 + bn);
        __syncthreads();
#pragma unroll
        for (int kk = 0; kk < 16; kk++) {
            float4 a  = *(const float4*)(&Ast[kk][ty * 4]);
            float4 bb = *(const float4*)(&Bs[kk][tx * 4]);
            unsigned long long b01 = pk(bb.x, bb.y), b23 = pk(bb.z, bb.w);
            unsigned long long ax = pk(a.x, a.x), ay = pk(a.y, a.y);
            unsigned long long az = pk(a.z, a.z), aw = pk(a.w, a.w);
            fma2(acc2[0][0], ax, b01); fma2(acc2[0][1], ax, b23);
            fma2(acc2[1][0], ay, b01); fma2(acc2[1][1], ay, b23);
            fma2(acc2[2][0], az, b01); fma2(acc2[2][1], az, b23);
            fma2(acc2[3][0], aw, b01); fma2(acc2[3][1], aw, b23);
        }
        __syncthreads();
    }
#pragma unroll
    for (int i = 0; i < 4; i++) {
        int row = m0 + ty * 4 + i;
        float2 v01 = upk(acc2[i][0]), v23 = upk(acc2[i][1]);
        float4 v;
        v.x = v01.x; v.y = v01.y; v.z = v23.x; v.w = v23.y;
        if (bias) {
            v.x += bias[n0 + tx * 4 + 0];
            v.y += bias[n0 + tx * 4 + 1];
            v.z += bias[n0 + tx * 4 + 2];
            v.w += bias[n0 + tx * 4 + 3];
        }
        *(float4*)(&C[(size_t)row * N + n0 + tx * 4]) = v;
    }
}

// -------- head GEMM: xa = hA[srcI]@Wa1 + hB[srcE]@Ua1 (K=512 fused gather) ----
__global__ void __launch_bounds__(256) gemm_head(
    const float* __restrict__ hA, const float* __restrict__ hB,
    const int* __restrict__ srcI,
    const float* __restrict__ Wa1, const float* __restrict__ Ua1,
    float* __restrict__ xa) {
    const int K = 256, N = ADIM;
    __shared__ __align__(16) float Ast[16][68];
    __shared__ __align__(16) float Bs[16][64];
    int t  = threadIdx.x;
    int m0 = blockIdx.y * 64;
    int n0 = blockIdx.x * 64;
    int ty = t >> 4, tx = t & 15;

    unsigned long long acc2[4][2];
#pragma unroll
    for (int i = 0; i < 4; i++) { acc2[i][0] = 0ull; acc2[i][1] = 0ull; }

    int ar = t >> 2;
    int ak = (t & 3) * 4;
    int arow = m0 + ar;
    int si = srcI ? srcI[arow] : arow;
    int se = g_srcE[arow];
    const float* pA = hA + (size_t)((si < 0) ? 0 : si) * K;
    const float* pB = hB + (size_t)((se < 0) ? 0 : se) * K;
    int bk = t >> 4;
    int bn = (t & 15) * 4;

#pragma unroll
    for (int pass = 0; pass < 2; pass++) {
        const float* Ap = (pass == 0) ? pA : pB;
        const bool valid = (pass == 0) ? (si >= 0) : (se >= 0);
        const float* Bp = (pass == 0) ? Wa1 : Ua1;
        for (int k0 = 0; k0 < K; k0 += 16) {
            float4 av = make_float4(0.f, 0.f, 0.f, 0.f);
            if (valid) av = *(const float4*)(Ap + k0 + ak);
            Ast[ak + 0][ar] = av.x;
            Ast[ak + 1][ar] = av.y;
            Ast[ak + 2][ar] = av.z;
            Ast[ak + 3][ar] = av.w;
            *(float4*)(&Bs[bk][bn]) = *(const float4*)(Bp + (size_t)(k0 + bk) * N + n0 + bn);
            __syncthreads();
#pragma unroll
            for (int kk = 0; kk < 16; kk++) {
                float4 a  = *(const float4*)(&Ast[kk][ty * 4]);
                float4 bb = *(const float4*)(&Bs[kk][tx * 4]);
                unsigned long long b01 = pk(bb.x, bb.y), b23 = pk(bb.z, bb.w);
                unsigned long long ax = pk(a.x, a.x), ay = pk(a.y, a.y);
                unsigned long long az = pk(a.z, a.z), aw = pk(a.w, a.w);
                fma2(acc2[0][0], ax, b01); fma2(acc2[0][1], ax, b23);
                fma2(acc2[1][0], ay, b01); fma2(acc2[1][1], ay, b23);
                fma2(acc2[2][0], az, b01); fma2(acc2[2][1], az, b23);
                fma2(acc2[3][0], aw, b01); fma2(acc2[3][1], aw, b23);
            }
            __syncthreads();
        }
    }
#pragma unroll
    for (int i = 0; i < 4; i++) {
        int row = m0 + ty * 4 + i;
        float2 v01 = upk(acc2[i][0]), v23 = upk(acc2[i][1]);
        float4 v;
        v.x = v01.x; v.y = v01.y; v.z = v23.x; v.w = v23.y;
        *(float4*)(&xa[(size_t)row * N + n0 + tx * 4]) = v;
    }
}

// -------------------- head: bulk action/policy + next mask --------------------
__global__ void head_kernel(int d, const float* __restrict__ lin,
                            const float* __restrict__ ba1,
                            const float* __restrict__ Wa2,
                            const float* __restrict__ ba2,
                            const float* __restrict__ hout,
                            float* __restrict__ out, int out_size) {
    int r = blockIdx.x;
    int l = r >> 6, b = r & 63;
    int t = threadIdx.x;           // 128
    __shared__ float s[8];

    float v = tanhf(lin[(size_t)r * ADIM + t] + ba1[t]);
    float p0 = warp_sum(v * Wa2[2 * t]);
    float p1 = warp_sum(v * Wa2[2 * t + 1]);
    if ((t & 31) == 0) { s[(t >> 5) * 2] = p0; s[(t >> 5) * 2 + 1] = p1; }

    if (d == DEPTH - 1 && l == LSEQ - 1 && out_size >= BATCH * HDIM) {
        int n = g_nsteps[b];
        int last = (n > 0) ? g_steplist[b * SL_STRIDE + n - 1] : -1;
        if (last >= 0) {
            const float* hr = hout + ((size_t)last * BATCH + b) * HDIM;
            out[b * HDIM + t]       = hr[t];
            out[b * HDIM + 128 + t] = hr[128 + t];
        } else {
            out[b * HDIM + t]       = 0.0f;
            out[b * HDIM + 128 + t] = 0.0f;
        }
    }
    __syncthreads();
    if (t == 0) {
        float l0 = s[0] + s[2] + s[4] + s[6] + ba2[0];
        float l1 = s[1] + s[3] + s[5] + s[7] + ba2[1];
        unsigned char mt = g_mask[b * LSEQ + l];
        unsigned char act = ((l1 > l0) && mt) ? 1 : 0;
        g_mask[b * LSEQ + l] = act;
        if (out_size >= 409600) {
            float m = fmaxf(l0, l1);
            float e0 = expf(l0 - m), e1 = expf(l1 - m);
            float inv = 1.0f / (e0 + e1);
            size_t ai = (size_t)BATCH * HDIM + ((size_t)(b * DEPTH + d)) * LSEQ + l;
            out[ai] = act ? 1.0f : 0.0f;
            size_t pi = (size_t)BATCH * HDIM + (size_t)BATCH * DEPTH * LSEQ +
                        (((size_t)(b * DEPTH + d)) * LSEQ + l) * 2;
            out[pi]     = e0 * inv;
            out[pi + 1] = e1 * inv;
        }
    }
}

// ------- cluster scan: col-aligned rows, local gates, tiny L2 exchange --------
// CTA rank owns U^T rows {64r..+63, 256+64r..+63, 512+64r..+63}. Gates for cols
// 64r..64r+63 are computed from LOCAL matvec outputs. Exchange per iter:
// 4 LN-partial floats (bar1) + 128 new-h floats (bar2) per CTA.
__global__ void __cluster_dims__(C4_NCTAS, 1, 1) __launch_bounds__(SCAN_THREADS, 1)
scan10_kernel(const float* __restrict__ bg,
              const float* __restrict__ gammas,
              const float* __restrict__ betas,
              float* __restrict__ hout) {
    extern __shared__ __align__(16) float sm[];
    float* Wsm    = sm;                         // 192*65*4 = 49920 floats
    float* s_hT   = Wsm + R4 * WROW4_F4 * 4;    // 528
    float* s_hploc= s_hT + 528;                 // 192*2 = 384
    float* s_xpa  = s_hploc + 384;              // 2*2*768 = 3072
    float* s_lnA  = s_xpa + 3072;               // 24*4 = 96
    float* s_xst  = s_lnA + 96;                 // 8 (2 par x 2 b x mu,rstd)
    int*   s_lb   = (int*)(s_xst + 8);          // 4 (2 par x 2 b)
    int*   s_off  = s_lb + 4;                   // 2
    int*   s_ns   = s_off + 2;                  // 2

    const int t    = threadIdx.x;
    const int rank = blockIdx.x & (C4_NCTAS - 1);
    const int clu  = blockIdx.x >> 2;
    const int b0   = clu * NB4;
    const int lane = t & 31, wid = t >> 5;

    // ---- weight slice: local row j -> global row (j/64)*256 + 64*rank + j%64 ----
    {
        const float4* src = (const float4*)g_Ut;
        float4* dst = (float4*)Wsm;
        for (int i = t; i < R4 * 64; i += SCAN_THREADS) {
            int row = i >> 6, c4 = i & 63;
            int grow = (row >> 6) * 256 + 64 * rank + (row & 63);
            dst[row * WROW4_F4 + c4] = src[(size_t)grow * 64 + c4];
        }
    }
    for (int i = t; i < 528; i += SCAN_THREADS) s_hT[i] = 0.0f;

    int maxit = 0;
#pragma unroll
    for (int i = 0; i < NB4; i++) {
        int n = g_nsteps[b0 + i];
        maxit = (n > maxit) ? n : maxit;
    }
    if (t < NB4) {
        s_lb[t]  = g_steplist[(b0 + t) * SL_STRIDE];
        s_off[t] = g_off[b0 + t];
        s_ns[t]  = g_nsteps[b0 + t];
    }
    __syncthreads();

    // prologue: xp(it=0) for 2 batches (384 f4)
    if (t < 384) {
        int bb = t / 192, c4 = t - 192 * bb;
        if (s_ns[bb] > 0)
            ((float4*)s_xpa)[t] =
                *((const float4*)g_xpc + (size_t)s_off[bb] * 192 + c4);
    }
    __syncthreads();
    if (t >= 768 && t < 832) {   // warps 24,25: xp stats it=0
        int u = t - 768, bb = u >> 5;
        const float* xr = s_xpa + bb * H3;
        float s = 0.f, q = 0.f;
#pragma unroll
        for (int j = 0; j < 24; j++) { float v = xr[(u & 31) + 32 * j]; s += v; q += v * v; }
        s = warp_sum(s); q = warp_sum(q);
        if ((u & 31) == 0) {
            float mu = s * (1.0f / 768.0f), var = q * (1.0f / 768.0f) - mu * mu;
            s_xst[bb * 2] = mu; s_xst[bb * 2 + 1] = rsqrtf(var + 1e-5f);
        }
    }
    __syncthreads();

    const int r_ = t >> 2, kq = t & 3;
    const float4* wf = (const float4*)Wsm + r_ * WROW4_F4 + kq * 16;
    const float4* ht = (const float4*)s_hT + kq * 33;
    float* gbase = g_hp + (size_t)clu * (2 * CLUBUF4);

    for (int it = 0; it < maxit; ++it) {
        const int par = it & 1, nxt = par ^ 1;
        float* gout = gbase + par * CLUBUF4;

        // ================ phase A: matvec (local rows) + LN partials ==========
        float4 pf0, pf1, pf2;
        if (t < 768) {
            float d0 = 0.f, d1 = 0.f;
#pragma unroll
            for (int i = 0; i < 16; i++) {
                float4 w  = wf[i];
                float4 h0 = ht[i * 2 + 0];
                float4 h1 = ht[i * 2 + 1];
                d0 += w.x * h0.x + w.y * h0.z;
                d1 += w.x * h0.y + w.y * h0.w;
                d0 += w.z * h1.x + w.w * h1.z;
                d1 += w.z * h1.y + w.w * h1.w;
            }
            d0 += __shfl_xor_sync(0xffffffffu, d0, 1);
            d1 += __shfl_xor_sync(0xffffffffu, d1, 1);
            d0 += __shfl_xor_sync(0xffffffffu, d0, 2);
            d1 += __shfl_xor_sync(0xffffffffu, d1, 2);
            if (kq == 0) {
                s_hploc[r_ * 2]     = d0;
                s_hploc[r_ * 2 + 1] = d1;
            }
            float q0 = d0 * d0, q1 = d1 * d1;
#pragma unroll
            for (int m = 4; m <= 16; m <<= 1) {
                d0 += __shfl_xor_sync(0xffffffffu, d0, m);
                d1 += __shfl_xor_sync(0xffffffffu, d1, m);
                q0 += __shfl_xor_sync(0xffffffffu, q0, m);
                q1 += __shfl_xor_sync(0xffffffffu, q1, m);
            }
            if (lane == 0) {
                s_lnA[wid * 4 + 0] = d0; s_lnA[wid * 4 + 1] = d1;
                s_lnA[wid * 4 + 2] = q0; s_lnA[wid * 4 + 3] = q1;
            }
        } else {
            int u = t - 768;
            if (u < NB4) s_lb[nxt * NB4 + u] = g_steplist[(b0 + u) * SL_STRIDE + it + 1];
            const float4* xpf4 = (const float4*)g_xpc;
#pragma unroll
            for (int j = 0; j < 3; j++) {
                int idx = u + 128 * j;
                int bb = idx / 192, c4 = idx - 192 * bb;
                float4 vv = make_float4(0.f, 0.f, 0.f, 0.f);
                if (it + 1 < s_ns[bb])
                    vv = xpf4[(size_t)(s_off[bb] + it + 1) * 192 + c4];
                if (j == 0) pf0 = vv; else if (j == 1) pf1 = vv; else pf2 = vv;
            }
        }
        __syncthreads();
        if (t < 4) {   // reduce LN partials, publish 4 floats
            float acc = 0.f;
#pragma unroll
            for (int w = 0; w < 24; w++) acc += s_lnA[w * 4 + t];
            gout[rank * G4_REC + t] = acc;   // [Sd0, Sd1, Sq0, Sq1]
        } else if (t >= 768) {   // store prefetched xp(it+1) into nxt buffer
            int u = t - 768;
            float4* xd = (float4*)(s_xpa + nxt * (NB4 * H3));
            xd[u + 0]   = pf0;
            xd[u + 128] = pf1;
            xd[u + 256] = pf2;
        }

        asm volatile("barrier.cluster.arrive.aligned;" ::: "memory");
        asm volatile("barrier.cluster.wait.aligned;" ::: "memory");

        // ============ gates: LOCAL (t<128: 64 cols x 2 batches) ================
        if (t < 128) {
            int bb = t >> 6, cl = t & 63;
            int col = 64 * rank + cl;
            // per-thread LN stats from the 16 published floats (own batch)
            float S = 0.f, Q = 0.f;
#pragma unroll
            for (int rr = 0; rr < 4; rr++) {
                S += __ldcv(gout + rr * G4_REC + bb);
                Q += __ldcv(gout + rr * G4_REC + 2 + bb);
            }
            float mu  = S * (1.0f / 768.0f);
            float var = Q * (1.0f / 768.0f) - mu * mu;
            float rs  = rsqrtf(var + 1e-5f);

            float hold = s_hT[HT2_FLT(col, bb)];
            float ho = hold;
            int lb = s_lb[par * NB4 + bb];
            if (lb >= 0) {
                float mux = s_xst[par * 4 + bb * 2], rsx = s_xst[par * 4 + bb * 2 + 1];
                const float* xr = s_xpa + par * (NB4 * H3) + bb * H3;
                float x0 = __ldg(gammas + col)       * (xr[col]       - mux) * rsx + __ldg(betas + col);
                float x1 = __ldg(gammas + col + 256) * (xr[col + 256] - mux) * rsx + __ldg(betas + col + 256);
                float x2 = __ldg(gammas + col + 512) * (xr[col + 512] - mux) * rsx + __ldg(betas + col + 512);
                float hp0 = (s_hploc[cl * 2 + bb]         - mu) * rs * __ldg(gammas + H3 + col)       + __ldg(betas + H3 + col);
                float hp1 = (s_hploc[(64 + cl) * 2 + bb]  - mu) * rs * __ldg(gammas + H3 + col + 256) + __ldg(betas + H3 + col + 256);
                float hp2 = (s_hploc[(128 + cl) * 2 + bb] - mu) * rs * __ldg(gammas + H3 + col + 512) + __ldg(betas + H3 + col + 512);
                float r  = fsig(x0 + hp0     + __ldg(bg + col));
                float z  = fsig(x1 + hp1     + __ldg(bg + col + 256));
                float hh = ftanhf(x2 + r * hp2 + __ldg(bg + col + 512));
                ho = z * hold + (1.0f - z) * hh;
                hout[((size_t)lb * BATCH + b0 + bb) * HDIM + col] = ho;
            }
            gout[rank * G4_REC + 4 + bb * 64 + cl] = ho;   // publish h slice
        } else if (t >= 768 && t < 832) {
            // xp stats for it+1 (from just-stored nxt buffer)
            int u = t - 768, bb = u >> 5;
            const float* xr = s_xpa + nxt * (NB4 * H3) + bb * H3;
            float s = 0.f, q = 0.f;
#pragma unroll
            for (int j = 0; j < 24; j++) { float v = xr[(u & 31) + 32 * j]; s += v; q += v * v; }
            s = warp_sum(s); q = warp_sum(q);
            if ((u & 31) == 0) {
                float mu = s * (1.0f / 768.0f), var = q * (1.0f / 768.0f) - mu * mu;
                s_xst[nxt * 4 + bb * 2] = mu;
                s_xst[nxt * 4 + bb * 2 + 1] = rsqrtf(var + 1e-5f);
            }
        }

        asm volatile("barrier.cluster.arrive.aligned;" ::: "memory");
        asm volatile("barrier.cluster.wait.aligned;" ::: "memory");

        // ============ assemble full h from 4 slices ============================
        if (t < 512) {
            int bb = t >> 8, col = t & 255;
            float v = __ldcv(gout + (col >> 6) * G4_REC + 4 + bb * 64 + (col & 63));
            s_hT[HT2_FLT(col, bb)] = v;
        }
        __syncthreads();   // s_hT / s_lb / s_xpa / s_xst stable for next iter
    }
}

// --------------------------------- launcher ----------------------------------
extern "C" void kernel_launch(void* const* d_in, const int* in_sizes, int n_in,
                              void* d_out, int out_size) {
    const float* x     = (const float*)d_in[0];
    const unsigned char* mask = (const unsigned char*)d_in[1];
    const float* W_emb = (const float*)d_in[2];
    const float* b_emb = (const float*)d_in[3];
    const float* W     = (const float*)d_in[4];
    const float* U     = (const float*)d_in[5];
    const float* bgate = (const float*)d_in[6];
    const float* Wa1   = (const float*)d_in[7];
    const float* Ua1   = (const float*)d_in[8];
    const float* ba1   = (const float*)d_in[9];
    const float* Wa2   = (const float*)d_in[10];
    const float* ba2   = (const float*)d_in[11];
    const float* gammas = (const float*)d_in[12];
    const float* betas  = (const float*)d_in[13];
    float* out = (float*)d_out;

    float *h0, *h1, *xpc, *xa;
    int *srcI;
    cudaGetSymbolAddress((void**)&h0, g_h0);
    cudaGetSymbolAddress((void**)&h1, g_h1);
    cudaGetSymbolAddress((void**)&xpc, g_xpc);
    cudaGetSymbolAddress((void**)&xa, g_xa);
    cudaGetSymbolAddress((void**)&srcI, g_srcI);

    const int scan_smem =
        (R4 * WROW4_F4 * 4 + 528 + 384 + 3072 + 96 + 8 + 4 + 2 + 2) * 4;
    static int attr_done = 0;
    if (!attr_done) {
        cudaFuncSetAttribute(scan10_kernel, cudaFuncAttributeMaxDynamicSharedMemorySize, scan_smem);
        attr_done = 1;
    }

    // launch order: 0 prep, 1 embed, 2 gemm_xp(compact), 3 SCAN (profiled), ...
    prep_fused<<<H3 + 1, HDIM>>>(U, mask);
    sgemm_kernel<1><<<dim3(HDIM / 64, NROWS / 64), 256>>>(x, W_emb, b_emb, h0, HDIM);

    for (int d = 0; d < DEPTH; d++) {
        float* hin  = (d & 1) ? h1 : h0;
        float* hout = (d & 1) ? h0 : h1;
        sgemm_kernel<3><<<dim3(H3 / 64, NROWS / 64), 256>>>(hin, W, nullptr, xpc, H3);
        scan10_kernel<<<NCLU4 * C4_NCTAS, SCAN_THREADS, scan_smem>>>(
            bgate, gammas, betas, hout);
        const int* sI = (d == 0) ? nullptr : (srcI + ((d - 1) & 1) * NROWS);
        gemm_head<<<dim3(ADIM / 64, NROWS / 64), 256>>>(hin, hout, sI, Wa1, Ua1, xa);
        head_kernel<<<NROWS, 128>>>(d, xa, ba1, Wa2, ba2, hout, out, out_size);
        if (d < DEPTH - 1) plan_kernel<<<1, 1024>>>((d + 1) & 1);
    }
}

// round 15
// speedup vs baseline: 1.0975x; 1.0975x over previous
#include <cuda_runtime.h>
#include <cuda_bf16.h>
#include <cstddef>
#include <cstdint>

// Problem constants (fixed by the dataset)
#define BATCH 64
#define LSEQ  512
#define DIN   256
#define HDIM  256
#define H3    768
#define ADIM  128
#define DEPTH 4
#define NROWS (LSEQ * BATCH)   // 32768

// ---- scan: 4-CTA clusters, 2 batches per cluster (R13 protocol) ----
#define C4_NCTAS   4
#define R4         192         // weight rows per CTA (768/4)
#define NB4        2           // batches per cluster
#define NCLU4      32
#define SCAN_THREADS 896
#define WROW4_F4   65          // 64 data f4 + 1 pad
#define G4_REC     392         // floats per rank record: 192*2 + 4 stats + pad
#define CLUBUF4    (C4_NCTAS * G4_REC)   // 1568 floats per parity
#define SL_STRIDE  520

// hT layout (2 batches): 4 k-blocks of 33 f4 (32 data + 1 pad)
#define HT2_FLT(c, b) ((((((c) >> 6) * 33) + (((c) & 63) >> 1)) << 2) + (((c) & 1) * 2) + (b))

// ---------------- scratch (device globals; no allocation allowed) -------------
__device__ float g_h0  [(size_t)NROWS * HDIM];
__device__ float g_h1  [(size_t)NROWS * HDIM];
__device__ float g_xpc [(size_t)(NROWS + 64) * H3];  // compacted xp (pre-normalized)
__device__ float g_xa  [(size_t)NROWS * ADIM];
__device__ float g_Ut  [(size_t)H3 * HDIM];          // U^T (768x256)
__device__ float g_hp  [(size_t)NCLU4 * 2 * CLUBUF4];
__device__ int   g_steplist[BATCH * SL_STRIDE];
__device__ int   g_nsteps[BATCH];
__device__ int   g_off  [BATCH + 1];
__device__ int   g_rowA [NROWS + 64];
__device__ int   g_srcE [NROWS];
__device__ int   g_srcI [2][NROWS];
__device__ int   g_mtotal;
__device__ unsigned char g_mask[BATCH * LSEQ];

// ---------------------------------- helpers ----------------------------------
__device__ __forceinline__ float warp_sum(float v) {
#pragma unroll
    for (int o = 16; o > 0; o >>= 1) v += __shfl_down_sync(0xffffffffu, v, o);
    return v;
}
__device__ __forceinline__ float fsig(float x) {
    float e = __expf(-x);
    return __fdividef(1.0f, 1.0f + e);
}
__device__ __forceinline__ float ftanhf(float x) {
    float e = __expf(2.0f * x);
    return 1.0f - __fdividef(2.0f, e + 1.0f);
}
__device__ __forceinline__ void fma2(unsigned long long& d, unsigned long long a,
                                     unsigned long long b) {
    asm("fma.rn.f32x2 %0, %1, %2, %0;" : "+l"(d) : "l"(a), "l"(b));
}
__device__ __forceinline__ unsigned long long pk(float lo, float hi) {
    unsigned long long r;
    asm("mov.b64 %0, {%1, %2};" : "=l"(r) : "f"(lo), "f"(hi));
    return r;
}
__device__ __forceinline__ float2 upk(unsigned long long v) {
    float2 r;
    asm("mov.b64 {%0, %1}, %2;" : "=f"(r.x), "=f"(r.y) : "l"(v));
    return r;
}

// ------------- per-batch plan body (lists, offsets, rowA, srcE, srcI) ---------
__device__ __forceinline__ void plan_batch(const unsigned char* m, int b, int ibuf) {
    int n = 0, src = -1;
    for (int l = 0; l < LSEQ; l++) {
        int prev = src;
        if (m[l]) { g_steplist[b * SL_STRIDE + n] = l; n++; src = l; }
        int r = l * BATCH + b;
        g_srcE[r]       = (prev < 0) ? -1 : prev * BATCH + b;
        g_srcI[ibuf][r] = (src  < 0) ? -1 : src  * BATCH + b;
    }
    g_nsteps[b] = n;
    for (int i = n; i <= LSEQ; i++) g_steplist[b * SL_STRIDE + i] = -1;
}

// ----------------- prep: U transpose + mask copy + depth-0 plan ---------------
__global__ void prep_fused(const float* __restrict__ U,
                           const unsigned char* __restrict__ m8) {
    int k = blockIdx.x;
    if (k < H3) {
        int i = threadIdx.x;
        g_Ut[(size_t)k * HDIM + i] = U[(size_t)i * H3 + k];
        return;
    }
    __shared__ unsigned char smm[BATCH * LSEQ];
    __shared__ int mode;
    int t = threadIdx.x;
    if (t == 0) {
        int nz = 0;
        for (int i = 0; i < 64; i++) nz |= m8[4 * i + 1] | m8[4 * i + 2] | m8[4 * i + 3];
        mode = nz ? 1 : 0;
    }
    __syncthreads();
    if (mode) {
        for (int i = t; i < BATCH * LSEQ; i += blockDim.x) {
            unsigned char v = m8[i] ? 1 : 0;
            g_mask[i] = v; smm[i] = v;
        }
    } else {
        const int* m32 = (const int*)m8;
        for (int i = t; i < BATCH * LSEQ; i += blockDim.x) {
            unsigned char v = m32[i] ? 1 : 0;
            g_mask[i] = v; smm[i] = v;
        }
    }
    __syncthreads();
    if (t < BATCH) plan_batch(smm + t * LSEQ, t, 0);
    __syncthreads();
    if (t == 0) {
        int acc = 0;
        for (int b = 0; b < BATCH; b++) { g_off[b] = acc; acc += g_nsteps[b]; }
        g_off[BATCH] = acc;
        g_mtotal = acc;
    }
    __syncthreads();
    if (t < BATCH) {
        int b = t, off = g_off[b], n = g_nsteps[b];
        for (int i = 0; i < n; i++)
            g_rowA[off + i] = g_steplist[b * SL_STRIDE + i] * BATCH + b;
    }
}

// ---------------- plan (d>=1): one block, everything ---------------------------
__global__ void plan_kernel(int ibuf) {
    __shared__ unsigned char smm[BATCH * LSEQ];
    int t = threadIdx.x;   // 1024
    for (int i = t; i < BATCH * LSEQ; i += blockDim.x) smm[i] = g_mask[i];
    __syncthreads();
    if (t < BATCH) plan_batch(smm + t * LSEQ, t, ibuf);
    __syncthreads();
    if (t == 0) {
        int acc = 0;
        for (int b = 0; b < BATCH; b++) { g_off[b] = acc; acc += g_nsteps[b]; }
        g_off[BATCH] = acc;
        g_mtotal = acc;
    }
    __syncthreads();
    if (t < BATCH) {
        int b = t, off = g_off[b], n = g_nsteps[b];
        for (int i = 0; i < n; i++)
            g_rowA[off + i] = g_steplist[b * SL_STRIDE + i] * BATCH + b;
    }
}

// ------------------------------- tiled SGEMM (f32x2) --------------------------
template <int MODE>
__global__ void __launch_bounds__(256) sgemm_kernel(
    const float* __restrict__ A, const float* __restrict__ Bm,
    const float* __restrict__ bias, float* __restrict__ C, int N) {
    const int K = 256;
    __shared__ __align__(16) float Ast[16][68];
    __shared__ __align__(16) float Bs[16][64];
    int t  = threadIdx.x;
    int m0 = blockIdx.y * 64;
    int n0 = blockIdx.x * 64;
    if (MODE == 3 && m0 >= g_mtotal) return;
    int ty = t >> 4, tx = t & 15;

    unsigned long long acc2[4][2];
#pragma unroll
    for (int i = 0; i < 4; i++) { acc2[i][0] = 0ull; acc2[i][1] = 0ull; }

    int ar = t >> 2;
    int ak = (t & 3) * 4;
    int arow = m0 + ar;
    const float* Aptr;
    if (MODE == 1) {
        int b = arow & 63, l = arow >> 6;
        Aptr = A + ((size_t)b * LSEQ + l) * K;
    } else {
        int mt = g_mtotal;
        int rr = (arow < mt) ? arow : (mt - 1);
        Aptr = A + (size_t)g_rowA[rr] * K;
    }
    int bk = t >> 4;
    int bn = (t & 15) * 4;

    for (int k0 = 0; k0 < K; k0 += 16) {
        float4 av = *(const float4*)(Aptr + k0 + ak);
        Ast[ak + 0][ar] = av.x;
        Ast[ak + 1][ar] = av.y;
        Ast[ak + 2][ar] = av.z;
        Ast[ak + 3][ar] = av.w;
        *(float4*)(&Bs[bk][bn]) = *(const float4*)(Bm + (size_t)(k0 + bk) * N + n0 + bn);
        __syncthreads();
#pragma unroll
        for (int kk = 0; kk < 16; kk++) {
            float4 a  = *(const float4*)(&Ast[kk][ty * 4]);
            float4 bb = *(const float4*)(&Bs[kk][tx * 4]);
            unsigned long long b01 = pk(bb.x, bb.y), b23 = pk(bb.z, bb.w);
            unsigned long long ax = pk(a.x, a.x), ay = pk(a.y, a.y);
            unsigned long long az = pk(a.z, a.z), aw = pk(a.w, a.w);
            fma2(acc2[0][0], ax, b01); fma2(acc2[0][1], ax, b23);
            fma2(acc2[1][0], ay, b01); fma2(acc2[1][1], ay, b23);
            fma2(acc2[2][0], az, b01); fma2(acc2[2][1], az, b23);
            fma2(acc2[3][0], aw, b01); fma2(acc2[3][1], aw, b23);
        }
        __syncthreads();
    }
#pragma unroll
    for (int i = 0; i < 4; i++) {
        int row = m0 + ty * 4 + i;
        float2 v01 = upk(acc2[i][0]), v23 = upk(acc2[i][1]);
        float4 v;
        v.x = v01.x; v.y = v01.y; v.z = v23.x; v.w = v23.y;
        if (bias) {
            v.x += bias[n0 + tx * 4 + 0];
            v.y += bias[n0 + tx * 4 + 1];
            v.z += bias[n0 + tx * 4 + 2];
            v.w += bias[n0 + tx * 4 + 3];
        }
        *(float4*)(&C[(size_t)row * N + n0 + tx * 4]) = v;
    }
}

// ------ lnx: in-place LN of compacted xp rows + gamma0/beta0 + gate bias ------
__global__ void __launch_bounds__(256) lnx_kernel(float* __restrict__ xpc,
                                                  const float* __restrict__ gammas,
                                                  const float* __restrict__ betas,
                                                  const float* __restrict__ bg) {
    int r = blockIdx.x;
    if (r >= g_mtotal) return;
    float* row = xpc + (size_t)r * H3;
    int t = threadIdx.x;  // 256
    float v0 = row[t], v1 = row[t + 256], v2 = row[t + 512];
    float s = v0 + v1 + v2;
    float q = v0 * v0 + v1 * v1 + v2 * v2;
    __shared__ float rs_[8], rq_[8];
    __shared__ float s_mu, s_rstd;
    float ws = warp_sum(s), wq = warp_sum(q);
    if ((t & 31) == 0) { rs_[t >> 5] = ws; rq_[t >> 5] = wq; }
    __syncthreads();
    if (t == 0) {
        float S = 0.f, Q = 0.f;
#pragma unroll
        for (int i = 0; i < 8; i++) { S += rs_[i]; Q += rq_[i]; }
        float mu  = S * (1.0f / 768.0f);
        float var = Q * (1.0f / 768.0f) - mu * mu;
        s_mu = mu;
        s_rstd = rsqrtf(var + 1e-5f);
    }
    __syncthreads();
    float mu = s_mu, rstd = s_rstd;
    row[t]       = gammas[t]       * (v0 - mu) * rstd + betas[t]       + bg[t];
    row[t + 256] = gammas[t + 256] * (v1 - mu) * rstd + betas[t + 256] + bg[t + 256];
    row[t + 512] = gammas[t + 512] * (v2 - mu) * rstd + betas[t + 512] + bg[t + 512];
}

// -------- head GEMM: xa = hA[srcI]@Wa1 + hB[srcE]@Ua1 (K=512 fused gather) ----
__global__ void __launch_bounds__(256) gemm_head(
    const float* __restrict__ hA, const float* __restrict__ hB,
    const int* __restrict__ srcI,
    const float* __restrict__ Wa1, const float* __restrict__ Ua1,
    float* __restrict__ xa) {
    const int K = 256, N = ADIM;
    __shared__ __align__(16) float Ast[16][68];
    __shared__ __align__(16) float Bs[16][64];
    int t  = threadIdx.x;
    int m0 = blockIdx.y * 64;
    int n0 = blockIdx.x * 64;
    int ty = t >> 4, tx = t & 15;

    unsigned long long acc2[4][2];
#pragma unroll
    for (int i = 0; i < 4; i++) { acc2[i][0] = 0ull; acc2[i][1] = 0ull; }

    int ar = t >> 2;
    int ak = (t & 3) * 4;
    int arow = m0 + ar;
    int si = srcI ? srcI[arow] : arow;
    int se = g_srcE[arow];
    const float* pA = hA + (size_t)((si < 0) ? 0 : si) * K;
    const float* pB = hB + (size_t)((se < 0) ? 0 : se) * K;
    int bk = t >> 4;
    int bn = (t & 15) * 4;

#pragma unroll
    for (int pass = 0; pass < 2; pass++) {
        const float* Ap = (pass == 0) ? pA : pB;
        const bool valid = (pass == 0) ? (si >= 0) : (se >= 0);
        const float* Bp = (pass == 0) ? Wa1 : Ua1;
        for (int k0 = 0; k0 < K; k0 += 16) {
            float4 av = make_float4(0.f, 0.f, 0.f, 0.f);
            if (valid) av = *(const float4*)(Ap + k0 + ak);
            Ast[ak + 0][ar] = av.x;
            Ast[ak + 1][ar] = av.y;
            Ast[ak + 2][ar] = av.z;
            Ast[ak + 3][ar] = av.w;
            *(float4*)(&Bs[bk][bn]) = *(const float4*)(Bp + (size_t)(k0 + bk) * N + n0 + bn);
            __syncthreads();
#pragma unroll
            for (int kk = 0; kk < 16; kk++) {
                float4 a  = *(const float4*)(&Ast[kk][ty * 4]);
                float4 bb = *(const float4*)(&Bs[kk][tx * 4]);
                unsigned long long b01 = pk(bb.x, bb.y), b23 = pk(bb.z, bb.w);
                unsigned long long ax = pk(a.x, a.x), ay = pk(a.y, a.y);
                unsigned long long az = pk(a.z, a.z), aw = pk(a.w, a.w);
                fma2(acc2[0][0], ax, b01); fma2(acc2[0][1], ax, b23);
                fma2(acc2[1][0], ay, b01); fma2(acc2[1][1], ay, b23);
                fma2(acc2[2][0], az, b01); fma2(acc2[2][1], az, b23);
                fma2(acc2[3][0], aw, b01); fma2(acc2[3][1], aw, b23);
            }
            __syncthreads();
        }
    }
#pragma unroll
    for (int i = 0; i < 4; i++) {
        int row = m0 + ty * 4 + i;
        float2 v01 = upk(acc2[i][0]), v23 = upk(acc2[i][1]);
        float4 v;
        v.x = v01.x; v.y = v01.y; v.z = v23.x; v.w = v23.y;
        *(float4*)(&xa[(size_t)row * N + n0 + tx * 4]) = v;
    }
}

// -------------------- head: bulk action/policy + next mask --------------------
__global__ void head_kernel(int d, const float* __restrict__ lin,
                            const float* __restrict__ ba1,
                            const float* __restrict__ Wa2,
                            const float* __restrict__ ba2,
                            const float* __restrict__ hout,
                            float* __restrict__ out, int out_size) {
    int r = blockIdx.x;
    int l = r >> 6, b = r & 63;
    int t = threadIdx.x;           // 128
    __shared__ float s[8];

    float v = tanhf(lin[(size_t)r * ADIM + t] + ba1[t]);
    float p0 = warp_sum(v * Wa2[2 * t]);
    float p1 = warp_sum(v * Wa2[2 * t + 1]);
    if ((t & 31) == 0) { s[(t >> 5) * 2] = p0; s[(t >> 5) * 2 + 1] = p1; }

    if (d == DEPTH - 1 && l == LSEQ - 1 && out_size >= BATCH * HDIM) {
        int n = g_nsteps[b];
        int last = (n > 0) ? g_steplist[b * SL_STRIDE + n - 1] : -1;
        if (last >= 0) {
            const float* hr = hout + ((size_t)last * BATCH + b) * HDIM;
            out[b * HDIM + t]       = hr[t];
            out[b * HDIM + 128 + t] = hr[128 + t];
        } else {
            out[b * HDIM + t]       = 0.0f;
            out[b * HDIM + 128 + t] = 0.0f;
        }
    }
    __syncthreads();
    if (t == 0) {
        float l0 = s[0] + s[2] + s[4] + s[6] + ba2[0];
        float l1 = s[1] + s[3] + s[5] + s[7] + ba2[1];
        unsigned char mt = g_mask[b * LSEQ + l];
        unsigned char act = ((l1 > l0) && mt) ? 1 : 0;
        g_mask[b * LSEQ + l] = act;
        if (out_size >= 409600) {
            float m = fmaxf(l0, l1);
            float e0 = expf(l0 - m), e1 = expf(l1 - m);
            float inv = 1.0f / (e0 + e1);
            size_t ai = (size_t)BATCH * HDIM + ((size_t)(b * DEPTH + d)) * LSEQ + l;
            out[ai] = act ? 1.0f : 0.0f;
            size_t pi = (size_t)BATCH * HDIM + (size_t)BATCH * DEPTH * LSEQ +
                        (((size_t)(b * DEPTH + d)) * LSEQ + l) * 2;
            out[pi]     = e0 * inv;
            out[pi + 1] = e1 * inv;
        }
    }
}

// ----------- cluster scan (R13 protocol): 4-CTA clusters, 2 batches -----------
// One cluster barrier per iteration; 4-record L2 exchange; xp pre-normalized
// (bias folded) so gates need no xp-LN math; helpers only prefetch.
__global__ void __cluster_dims__(C4_NCTAS, 1, 1) __launch_bounds__(SCAN_THREADS, 1)
scan11_kernel(const float* __restrict__ gammas,
              const float* __restrict__ betas,
              float* __restrict__ hout) {
    extern __shared__ __align__(16) float sm[];
    float* Wsm   = sm;                         // 192*65*4 = 49920 floats
    float* s_hT  = Wsm + R4 * WROW4_F4 * 4;    // 528
    float* s_hp  = s_hT + 528;                 // 768*3 = 2304
    float* s_xpa = s_hp + 2304;                // 2*2*768 = 3072
    float* s_lnA = s_xpa + 3072;               // 24*4 = 96
    float* s_stat= s_lnA + 96;                 // 4 (2 b x mu,rstd)
    int*   s_lb  = (int*)(s_stat + 4);         // 4 (2 par x 2 b)
    int*   s_off = s_lb + 4;                   // 2
    int*   s_ns  = s_off + 2;                  // 2

    const int t    = threadIdx.x;
    const int rank = blockIdx.x & (C4_NCTAS - 1);
    const int clu  = blockIdx.x >> 2;
    const int b0   = clu * NB4;
    const int lane = t & 31, wid = t >> 5;

    // ---- weight slice (rows 192*rank..+191 of U^T), 65-f4 padded rows ----
    {
        const float4* src = (const float4*)(g_Ut + (size_t)(R4 * rank) * HDIM);
        float4* dst = (float4*)Wsm;
        for (int i = t; i < R4 * 64; i += SCAN_THREADS) {
            int row = i >> 6, c4 = i & 63;
            dst[row * WROW4_F4 + c4] = src[(size_t)row * 64 + c4];
        }
    }
    for (int i = t; i < 528; i += SCAN_THREADS) s_hT[i] = 0.0f;

    int maxit = 0;
#pragma unroll
    for (int i = 0; i < NB4; i++) {
        int n = g_nsteps[b0 + i];
        maxit = (n > maxit) ? n : maxit;
    }
    if (t < NB4) {
        s_lb[t]  = g_steplist[(b0 + t) * SL_STRIDE];
        s_off[t] = g_off[b0 + t];
        s_ns[t]  = g_nsteps[b0 + t];
    }
    __syncthreads();

    // prologue: xp(it=0) for 2 batches (384 f4) — already normalized + biased
    if (t < 384) {
        int bb = t / 192, c4 = t - 192 * bb;
        if (s_ns[bb] > 0)
            ((float4*)s_xpa)[t] =
                *((const float4*)g_xpc + (size_t)s_off[bb] * 192 + c4);
    }
    __syncthreads();

    // matvec mapping: thread = (row r_, K-quarter kq)
    const int r_ = t >> 2, kq = t & 3;
    const float4* wf = (const float4*)Wsm + r_ * WROW4_F4 + kq * 16;
    const float4* ht = (const float4*)s_hT + kq * 33;
    float* gbase = g_hp + (size_t)clu * (2 * CLUBUF4);

    for (int it = 0; it < maxit; ++it) {
        const int par = it & 1, nxt = par ^ 1;
        float* gout = gbase + par * CLUBUF4;

        // ================ phase A ================
        float4 pf0, pf1, pf2;
        if (t < 768) {
            float d0 = 0.f, d1 = 0.f;
#pragma unroll
            for (int i = 0; i < 16; i++) {
                float4 w  = wf[i];
                float4 h0 = ht[i * 2 + 0];   // [h(k)b0,h(k)b1,h(k+1)b0,h(k+1)b1]
                float4 h1 = ht[i * 2 + 1];
                d0 += w.x * h0.x + w.y * h0.z;
                d1 += w.x * h0.y + w.y * h0.w;
                d0 += w.z * h1.x + w.w * h1.z;
                d1 += w.z * h1.y + w.w * h1.w;
            }
            d0 += __shfl_xor_sync(0xffffffffu, d0, 1);
            d1 += __shfl_xor_sync(0xffffffffu, d1, 1);
            d0 += __shfl_xor_sync(0xffffffffu, d0, 2);
            d1 += __shfl_xor_sync(0xffffffffu, d1, 2);
            if (kq == 0)
                ((float2*)gout)[rank * (G4_REC / 2) + r_] = make_float2(d0, d1);
            float q0 = d0 * d0, q1 = d1 * d1;
#pragma unroll
            for (int m = 4; m <= 16; m <<= 1) {
                d0 += __shfl_xor_sync(0xffffffffu, d0, m);
                d1 += __shfl_xor_sync(0xffffffffu, d1, m);
                q0 += __shfl_xor_sync(0xffffffffu, q0, m);
                q1 += __shfl_xor_sync(0xffffffffu, q1, m);
            }
            if (lane == 0) {
                s_lnA[wid * 4 + 0] = d0; s_lnA[wid * 4 + 1] = d1;
                s_lnA[wid * 4 + 2] = q0; s_lnA[wid * 4 + 3] = q1;
            }
        } else {
            // helpers: next step indices + prefetch compacted xp(it+1)
            int u = t - 768;
            if (u < NB4) s_lb[nxt * NB4 + u] = g_steplist[(b0 + u) * SL_STRIDE + it + 1];
            const float4* xpf4 = (const float4*)g_xpc;
#pragma unroll
            for (int j = 0; j < 3; j++) {
                int idx = u + 128 * j;        // 0..383
                int bb = idx / 192, c4 = idx - 192 * bb;
                float4 vv = make_float4(0.f, 0.f, 0.f, 0.f);
                if (it + 1 < s_ns[bb])
                    vv = xpf4[(size_t)(s_off[bb] + it + 1) * 192 + c4];
                if (j == 0) pf0 = vv; else if (j == 1) pf1 = vv; else pf2 = vv;
            }
        }
        __syncthreads();
        if (t < 4) {
            float acc = 0.f;
#pragma unroll
            for (int w = 0; w < 24; w++) acc += s_lnA[w * 4 + t];
            gout[rank * G4_REC + 384 + t] = acc;   // [Sd0, Sd1, Sq0, Sq1]
        }

        asm volatile("barrier.cluster.arrive.aligned;" ::: "memory");
        asm volatile("barrier.cluster.wait.aligned;" ::: "memory");

        // ============ gather phase ============
        if (t < 768) {
            int rank_r = t / R4, wrow_r = t - R4 * rank_r;
            float2 v = __ldcv((const float2*)gout + rank_r * (G4_REC / 2) + wrow_r);
            s_hp[t * 3]     = v.x;
            s_hp[t * 3 + 1] = v.y;
            if (t < 2) {   // hp LN stats for batch t
                float S = 0.f, Q = 0.f;
#pragma unroll
                for (int rr = 0; rr < 4; rr++) {
                    S += __ldcv(gout + rr * G4_REC + 384 + t);
                    Q += __ldcv(gout + rr * G4_REC + 386 + t);
                }
                float mu  = S * (1.0f / 768.0f);
                float var = Q * (1.0f / 768.0f) - mu * mu;
                s_stat[t * 2]     = mu;
                s_stat[t * 2 + 1] = rsqrtf(var + 1e-5f);
            }
        } else {
            int u = t - 768;
            float4* xd = (float4*)(s_xpa + nxt * (NB4 * H3));
            xd[u + 0]   = pf0;
            xd[u + 128] = pf1;
            xd[u + 256] = pf2;
        }
        __syncthreads();

        // ============ gates (t<512, one item; xp pre-normalized) ==============
        if (t < 512) {
            int bb = t >> 8, col = t & 255;
            int lb = s_lb[par * NB4 + bb];
            if (lb >= 0) {
                float mu = s_stat[bb * 2], rs = s_stat[bb * 2 + 1];
                const float* xr = s_xpa + par * (NB4 * H3) + bb * H3;
                float hp0 = (s_hp[col * 3 + bb]         - mu) * rs * __ldg(gammas + H3 + col)       + __ldg(betas + H3 + col);
                float hp1 = (s_hp[(col + 256) * 3 + bb] - mu) * rs * __ldg(gammas + H3 + col + 256) + __ldg(betas + H3 + col + 256);
                float hp2 = (s_hp[(col + 512) * 3 + bb] - mu) * rs * __ldg(gammas + H3 + col + 512) + __ldg(betas + H3 + col + 512);
                float r  = fsig(xr[col]       + hp0);
                float z  = fsig(xr[col + 256] + hp1);
                float hh = ftanhf(xr[col + 512] + r * hp2);
                float hold = s_hT[HT2_FLT(col, bb)];
                float ho = z * hold + (1.0f - z) * hh;
                s_hT[HT2_FLT(col, bb)] = ho;
                if (rank == bb)
                    hout[((size_t)lb * BATCH + b0 + bb) * HDIM + col] = ho;
            }
        }
        __syncthreads();   // s_hT / s_lb / s_xpa stable for next iter
    }
}

// --------------------------------- launcher ----------------------------------
extern "C" void kernel_launch(void* const* d_in, const int* in_sizes, int n_in,
                              void* d_out, int out_size) {
    const float* x     = (const float*)d_in[0];
    const unsigned char* mask = (const unsigned char*)d_in[1];
    const float* W_emb = (const float*)d_in[2];
    const float* b_emb = (const float*)d_in[3];
    const float* W     = (const float*)d_in[4];
    const float* U     = (const float*)d_in[5];
    const float* bgate = (const float*)d_in[6];
    const float* Wa1   = (const float*)d_in[7];
    const float* Ua1   = (const float*)d_in[8];
    const float* ba1   = (const float*)d_in[9];
    const float* Wa2   = (const float*)d_in[10];
    const float* ba2   = (const float*)d_in[11];
    const float* gammas = (const float*)d_in[12];
    const float* betas  = (const float*)d_in[13];
    float* out = (float*)d_out;

    float *h0, *h1, *xpc, *xa;
    int *srcI;
    cudaGetSymbolAddress((void**)&h0, g_h0);
    cudaGetSymbolAddress((void**)&h1, g_h1);
    cudaGetSymbolAddress((void**)&xpc, g_xpc);
    cudaGetSymbolAddress((void**)&xa, g_xa);
    cudaGetSymbolAddress((void**)&srcI, g_srcI);

    const int scan_smem =
        (R4 * WROW4_F4 * 4 + 528 + 2304 + 3072 + 96 + 4 + 4 + 2 + 2) * 4;
    static int attr_done = 0;
    if (!attr_done) {
        cudaFuncSetAttribute(scan11_kernel, cudaFuncAttributeMaxDynamicSharedMemorySize, scan_smem);
        attr_done = 1;
    }

    prep_fused<<<H3 + 1, HDIM>>>(U, mask);
    sgemm_kernel<1><<<dim3(HDIM / 64, NROWS / 64), 256>>>(x, W_emb, b_emb, h0, HDIM);

    for (int d = 0; d < DEPTH; d++) {
        float* hin  = (d & 1) ? h1 : h0;
        float* hout = (d & 1) ? h0 : h1;
        sgemm_kernel<3><<<dim3(H3 / 64, NROWS / 64), 256>>>(hin, W, nullptr, xpc, H3);
        lnx_kernel<<<NROWS, 256>>>(xpc, gammas, betas, bgate);
        scan11_kernel<<<NCLU4 * C4_NCTAS, SCAN_THREADS, scan_smem>>>(
            gammas, betas, hout);
        const int* sI = (d == 0) ? nullptr : (srcI + ((d - 1) & 1) * NROWS);
        gemm_head<<<dim3(ADIM / 64, NROWS / 64), 256>>>(hin, hout, sI, Wa1, Ua1, xa);
        head_kernel<<<NROWS, 128>>>(d, xa, ba1, Wa2, ba2, hout, out, out_size);
        if (d < DEPTH - 1) plan_kernel<<<1, 1024>>>((d + 1) & 1);
    }
}

// round 16
// speedup vs baseline: 1.1134x; 1.0145x over previous
#include <cuda_runtime.h>
#include <cuda_bf16.h>
#include <cstddef>
#include <cstdint>

// Problem constants (fixed by the dataset)
#define BATCH 64
#define LSEQ  512
#define DIN   256
#define HDIM  256
#define H3    768
#define ADIM  128
#define DEPTH 4
#define NROWS (LSEQ * BATCH)   // 32768

// ---- scan: 4-CTA clusters, 2 batches per cluster (R13 protocol) ----
#define C4_NCTAS   4
#define R4         192         // weight rows per CTA (768/4)
#define NB4        2           // batches per cluster
#define NCLU4      32
#define SCAN_THREADS 896
#define WROW4_F4   65          // 64 data f4 + 1 pad
#define G4_REC     392         // floats per rank record: 192*2 + 4 stats + pad
#define CLUBUF4    (C4_NCTAS * G4_REC)   // 1568 floats per parity
#define SL_STRIDE  520

// hT layout (2 batches): 4 k-blocks of 33 f4 (32 data + 1 pad)
#define HT2_FLT(c, b) ((((((c) >> 6) * 33) + (((c) & 63) >> 1)) << 2) + (((c) & 1) * 2) + (b))

// ---------------- scratch (device globals; no allocation allowed) -------------
__device__ float g_h0  [(size_t)NROWS * HDIM];
__device__ float g_h1  [(size_t)NROWS * HDIM];
__device__ float g_xpc [(size_t)(NROWS + 64) * H3];  // compacted xp (pre-normalized)
__device__ float g_xa  [(size_t)NROWS * ADIM];
__device__ float g_Ut  [(size_t)H3 * HDIM];          // U^T (768x256)
__device__ float g_hp  [(size_t)NCLU4 * 2 * CLUBUF4];
__device__ int   g_steplist[BATCH * SL_STRIDE];
__device__ int   g_nsteps[BATCH];
__device__ int   g_off  [BATCH + 1];
__device__ int   g_rowA [NROWS + 64];
__device__ int   g_srcE [NROWS];
__device__ int   g_srcI [2][NROWS];
__device__ int   g_mtotal;
__device__ unsigned char g_mask[BATCH * LSEQ];

// ---------------------------------- helpers ----------------------------------
__device__ __forceinline__ float warp_sum(float v) {
#pragma unroll
    for (int o = 16; o > 0; o >>= 1) v += __shfl_down_sync(0xffffffffu, v, o);
    return v;
}
__device__ __forceinline__ float fsig(float x) {
    float e = __expf(-x);
    return __fdividef(1.0f, 1.0f + e);
}
__device__ __forceinline__ float ftanhf(float x) {
    float e = __expf(2.0f * x);
    return 1.0f - __fdividef(2.0f, e + 1.0f);
}
__device__ __forceinline__ void fma2(unsigned long long& d, unsigned long long a,
                                     unsigned long long b) {
    asm("fma.rn.f32x2 %0, %1, %2, %0;" : "+l"(d) : "l"(a), "l"(b));
}
__device__ __forceinline__ unsigned long long pk(float lo, float hi) {
    unsigned long long r;
    asm("mov.b64 %0, {%1, %2};" : "=l"(r) : "f"(lo), "f"(hi));
    return r;
}
__device__ __forceinline__ float2 upk(unsigned long long v) {
    float2 r;
    asm("mov.b64 {%0, %1}, %2;" : "=f"(r.x), "=f"(r.y) : "l"(v));
    return r;
}

// ------------- per-batch plan body (lists, offsets, rowA, srcE, srcI) ---------
__device__ __forceinline__ void plan_batch(const unsigned char* m, int b, int ibuf) {
    int n = 0, src = -1;
    for (int l = 0; l < LSEQ; l++) {
        int prev = src;
        if (m[l]) { g_steplist[b * SL_STRIDE + n] = l; n++; src = l; }
        int r = l * BATCH + b;
        g_srcE[r]       = (prev < 0) ? -1 : prev * BATCH + b;
        g_srcI[ibuf][r] = (src  < 0) ? -1 : src  * BATCH + b;
    }
    g_nsteps[b] = n;
    for (int i = n; i <= LSEQ; i++) g_steplist[b * SL_STRIDE + i] = -1;
}

// ----------------- prep: U transpose + mask copy + depth-0 plan ---------------
__global__ void prep_fused(const float* __restrict__ U,
                           const unsigned char* __restrict__ m8) {
    int k = blockIdx.x;
    if (k < H3) {
        int i = threadIdx.x;
        g_Ut[(size_t)k * HDIM + i] = U[(size_t)i * H3 + k];
        return;
    }
    __shared__ unsigned char smm[BATCH * LSEQ];
    __shared__ int mode;
    int t = threadIdx.x;
    if (t == 0) {
        int nz = 0;
        for (int i = 0; i < 64; i++) nz |= m8[4 * i + 1] | m8[4 * i + 2] | m8[4 * i + 3];
        mode = nz ? 1 : 0;
    }
    __syncthreads();
    if (mode) {
        for (int i = t; i < BATCH * LSEQ; i += blockDim.x) {
            unsigned char v = m8[i] ? 1 : 0;
            g_mask[i] = v; smm[i] = v;
        }
    } else {
        const int* m32 = (const int*)m8;
        for (int i = t; i < BATCH * LSEQ; i += blockDim.x) {
            unsigned char v = m32[i] ? 1 : 0;
            g_mask[i] = v; smm[i] = v;
        }
    }
    __syncthreads();
    if (t < BATCH) plan_batch(smm + t * LSEQ, t, 0);
    __syncthreads();
    if (t == 0) {
        int acc = 0;
        for (int b = 0; b < BATCH; b++) { g_off[b] = acc; acc += g_nsteps[b]; }
        g_off[BATCH] = acc;
        g_mtotal = acc;
    }
    __syncthreads();
    if (t < BATCH) {
        int b = t, off = g_off[b], n = g_nsteps[b];
        for (int i = 0; i < n; i++)
            g_rowA[off + i] = g_steplist[b * SL_STRIDE + i] * BATCH + b;
    }
}

// ---------------- plan (d>=1): one block, everything ---------------------------
__global__ void plan_kernel(int ibuf) {
    __shared__ unsigned char smm[BATCH * LSEQ];
    int t = threadIdx.x;   // 1024
    for (int i = t; i < BATCH * LSEQ; i += blockDim.x) smm[i] = g_mask[i];
    __syncthreads();
    if (t < BATCH) plan_batch(smm + t * LSEQ, t, ibuf);
    __syncthreads();
    if (t == 0) {
        int acc = 0;
        for (int b = 0; b < BATCH; b++) { g_off[b] = acc; acc += g_nsteps[b]; }
        g_off[BATCH] = acc;
        g_mtotal = acc;
    }
    __syncthreads();
    if (t < BATCH) {
        int b = t, off = g_off[b], n = g_nsteps[b];
        for (int i = 0; i < n; i++)
            g_rowA[off + i] = g_steplist[b * SL_STRIDE + i] * BATCH + b;
    }
}

// ------------------------------- tiled SGEMM (f32x2) --------------------------
template <int MODE>
__global__ void __launch_bounds__(256) sgemm_kernel(
    const float* __restrict__ A, const float* __restrict__ Bm,
    const float* __restrict__ bias, float* __restrict__ C, int N) {
    const int K = 256;
    __shared__ __align__(16) float Ast[16][68];
    __shared__ __align__(16) float Bs[16][64];
    int t  = threadIdx.x;
    int m0 = blockIdx.y * 64;
    int n0 = blockIdx.x * 64;
    if (MODE == 3 && m0 >= g_mtotal) return;
    int ty = t >> 4, tx = t & 15;

    unsigned long long acc2[4][2];
#pragma unroll
    for (int i = 0; i < 4; i++) { acc2[i][0] = 0ull; acc2[i][1] = 0ull; }

    int ar = t >> 2;
    int ak = (t & 3) * 4;
    int arow = m0 + ar;
    const float* Aptr;
    if (MODE == 1) {
        int b = arow & 63, l = arow >> 6;
        Aptr = A + ((size_t)b * LSEQ + l) * K;
    } else {
        int mt = g_mtotal;
        int rr = (arow < mt) ? arow : (mt - 1);
        Aptr = A + (size_t)g_rowA[rr] * K;
    }
    int bk = t >> 4;
    int bn = (t & 15) * 4;

    for (int k0 = 0; k0 < K; k0 += 16) {
        float4 av = *(const float4*)(Aptr + k0 + ak);
        Ast[ak + 0][ar] = av.x;
        Ast[ak + 1][ar] = av.y;
        Ast[ak + 2][ar] = av.z;
        Ast[ak + 3][ar] = av.w;
        *(float4*)(&Bs[bk][bn]) = *(const float4*)(Bm + (size_t)(k0 + bk) * N + n0 + bn);
        __syncthreads();
#pragma unroll
        for (int kk = 0; kk < 16; kk++) {
            float4 a  = *(const float4*)(&Ast[kk][ty * 4]);
            float4 bb = *(const float4*)(&Bs[kk][tx * 4]);
            unsigned long long b01 = pk(bb.x, bb.y), b23 = pk(bb.z, bb.w);
            unsigned long long ax = pk(a.x, a.x), ay = pk(a.y, a.y);
            unsigned long long az = pk(a.z, a.z), aw = pk(a.w, a.w);
            fma2(acc2[0][0], ax, b01); fma2(acc2[0][1], ax, b23);
            fma2(acc2[1][0], ay, b01); fma2(acc2[1][1], ay, b23);
            fma2(acc2[2][0], az, b01); fma2(acc2[2][1], az, b23);
            fma2(acc2[3][0], aw, b01); fma2(acc2[3][1], aw, b23);
        }
        __syncthreads();
    }
#pragma unroll
    for (int i = 0; i < 4; i++) {
        int row = m0 + ty * 4 + i;
        float2 v01 = upk(acc2[i][0]), v23 = upk(acc2[i][1]);
        float4 v;
        v.x = v01.x; v.y = v01.y; v.z = v23.x; v.w = v23.y;
        if (bias) {
            v.x += bias[n0 + tx * 4 + 0];
            v.y += bias[n0 + tx * 4 + 1];
            v.z += bias[n0 + tx * 4 + 2];
            v.w += bias[n0 + tx * 4 + 3];
        }
        *(float4*)(&C[(size_t)row * N + n0 + tx * 4]) = v;
    }
}

// ------ lnx: in-place LN of compacted xp rows + gamma0/beta0 + gate bias ------
__global__ void __launch_bounds__(256) lnx_kernel(float* __restrict__ xpc,
                                                  const float* __restrict__ gammas,
                                                  const float* __restrict__ betas,
                                                  const float* __restrict__ bg) {
    int r = blockIdx.x;
    if (r >= g_mtotal) return;
    float* row = xpc + (size_t)r * H3;
    int t = threadIdx.x;  // 256
    float v0 = row[t], v1 = row[t + 256], v2 = row[t + 512];
    float s = v0 + v1 + v2;
    float q = v0 * v0 + v1 * v1 + v2 * v2;
    __shared__ float rs_[8], rq_[8];
    __shared__ float s_mu, s_rstd;
    float ws = warp_sum(s), wq = warp_sum(q);
    if ((t & 31) == 0) { rs_[t >> 5] = ws; rq_[t >> 5] = wq; }
    __syncthreads();
    if (t == 0) {
        float S = 0.f, Q = 0.f;
#pragma unroll
        for (int i = 0; i < 8; i++) { S += rs_[i]; Q += rq_[i]; }
        float mu  = S * (1.0f / 768.0f);
        float var = Q * (1.0f / 768.0f) - mu * mu;
        s_mu = mu;
        s_rstd = rsqrtf(var + 1e-5f);
    }
    __syncthreads();
    float mu = s_mu, rstd = s_rstd;
    row[t]       = gammas[t]       * (v0 - mu) * rstd + betas[t]       + bg[t];
    row[t + 256] = gammas[t + 256] * (v1 - mu) * rstd + betas[t + 256] + bg[t + 256];
    row[t + 512] = gammas[t + 512] * (v2 - mu) * rstd + betas[t + 512] + bg[t + 512];
}

// -------- head GEMM: xa = hA[srcI]@Wa1 + hB[srcE]@Ua1 (K=512 fused gather) ----
__global__ void __launch_bounds__(256) gemm_head(
    const float* __restrict__ hA, const float* __restrict__ hB,
    const int* __restrict__ srcI,
    const float* __restrict__ Wa1, const float* __restrict__ Ua1,
    float* __restrict__ xa) {
    const int K = 256, N = ADIM;
    __shared__ __align__(16) float Ast[16][68];
    __shared__ __align__(16) float Bs[16][64];
    int t  = threadIdx.x;
    int m0 = blockIdx.y * 64;
    int n0 = blockIdx.x * 64;
    int ty = t >> 4, tx = t & 15;

    unsigned long long acc2[4][2];
#pragma unroll
    for (int i = 0; i < 4; i++) { acc2[i][0] = 0ull; acc2[i][1] = 0ull; }

    int ar = t >> 2;
    int ak = (t & 3) * 4;
    int arow = m0 + ar;
    int si = srcI ? srcI[arow] : arow;
    int se = g_srcE[arow];
    const float* pA = hA + (size_t)((si < 0) ? 0 : si) * K;
    const float* pB = hB + (size_t)((se < 0) ? 0 : se) * K;
    int bk = t >> 4;
    int bn = (t & 15) * 4;

#pragma unroll
    for (int pass = 0; pass < 2; pass++) {
        const float* Ap = (pass == 0) ? pA : pB;
        const bool valid = (pass == 0) ? (si >= 0) : (se >= 0);
        const float* Bp = (pass == 0) ? Wa1 : Ua1;
        for (int k0 = 0; k0 < K; k0 += 16) {
            float4 av = make_float4(0.f, 0.f, 0.f, 0.f);
            if (valid) av = *(const float4*)(Ap + k0 + ak);
            Ast[ak + 0][ar] = av.x;
            Ast[ak + 1][ar] = av.y;
            Ast[ak + 2][ar] = av.z;
            Ast[ak + 3][ar] = av.w;
            *(float4*)(&Bs[bk][bn]) = *(const float4*)(Bp + (size_t)(k0 + bk) * N + n0 + bn);
            __syncthreads();
#pragma unroll
            for (int kk = 0; kk < 16; kk++) {
                float4 a  = *(const float4*)(&Ast[kk][ty * 4]);
                float4 bb = *(const float4*)(&Bs[kk][tx * 4]);
                unsigned long long b01 = pk(bb.x, bb.y), b23 = pk(bb.z, bb.w);
                unsigned long long ax = pk(a.x, a.x), ay = pk(a.y, a.y);
                unsigned long long az = pk(a.z, a.z), aw = pk(a.w, a.w);
                fma2(acc2[0][0], ax, b01); fma2(acc2[0][1], ax, b23);
                fma2(acc2[1][0], ay, b01); fma2(acc2[1][1], ay, b23);
                fma2(acc2[2][0], az, b01); fma2(acc2[2][1], az, b23);
                fma2(acc2[3][0], aw, b01); fma2(acc2[3][1], aw, b23);
            }
            __syncthreads();
        }
    }
#pragma unroll
    for (int i = 0; i < 4; i++) {
        int row = m0 + ty * 4 + i;
        float2 v01 = upk(acc2[i][0]), v23 = upk(acc2[i][1]);
        float4 v;
        v.x = v01.x; v.y = v01.y; v.z = v23.x; v.w = v23.y;
        *(float4*)(&xa[(size_t)row * N + n0 + tx * 4]) = v;
    }
}

// -------------------- head: bulk action/policy + next mask --------------------
__global__ void head_kernel(int d, const float* __restrict__ lin,
                            const float* __restrict__ ba1,
                            const float* __restrict__ Wa2,
                            const float* __restrict__ ba2,
                            const float* __restrict__ hout,
                            float* __restrict__ out, int out_size) {
    int r = blockIdx.x;
    int l = r >> 6, b = r & 63;
    int t = threadIdx.x;           // 128
    __shared__ float s[8];

    float v = tanhf(lin[(size_t)r * ADIM + t] + ba1[t]);
    float p0 = warp_sum(v * Wa2[2 * t]);
    float p1 = warp_sum(v * Wa2[2 * t + 1]);
    if ((t & 31) == 0) { s[(t >> 5) * 2] = p0; s[(t >> 5) * 2 + 1] = p1; }

    if (d == DEPTH - 1 && l == LSEQ - 1 && out_size >= BATCH * HDIM) {
        int n = g_nsteps[b];
        int last = (n > 0) ? g_steplist[b * SL_STRIDE + n - 1] : -1;
        if (last >= 0) {
            const float* hr = hout + ((size_t)last * BATCH + b) * HDIM;
            out[b * HDIM + t]       = hr[t];
            out[b * HDIM + 128 + t] = hr[128 + t];
        } else {
            out[b * HDIM + t]       = 0.0f;
            out[b * HDIM + 128 + t] = 0.0f;
        }
    }
    __syncthreads();
    if (t == 0) {
        float l0 = s[0] + s[2] + s[4] + s[6] + ba2[0];
        float l1 = s[1] + s[3] + s[5] + s[7] + ba2[1];
        unsigned char mt = g_mask[b * LSEQ + l];
        unsigned char act = ((l1 > l0) && mt) ? 1 : 0;
        g_mask[b * LSEQ + l] = act;
        if (out_size >= 409600) {
            float m = fmaxf(l0, l1);
            float e0 = expf(l0 - m), e1 = expf(l1 - m);
            float inv = 1.0f / (e0 + e1);
            size_t ai = (size_t)BATCH * HDIM + ((size_t)(b * DEPTH + d)) * LSEQ + l;
            out[ai] = act ? 1.0f : 0.0f;
            size_t pi = (size_t)BATCH * HDIM + (size_t)BATCH * DEPTH * LSEQ +
                        (((size_t)(b * DEPTH + d)) * LSEQ + l) * 2;
            out[pi]     = e0 * inv;
            out[pi + 1] = e1 * inv;
        }
    }
}

// ----------- cluster scan (R13 protocol): 4-CTA clusters, 2 batches -----------
// One cluster barrier per iteration; 4-record L2 exchange; xp pre-normalized.
// gamma1/beta1 SMEM-resident (cluster barrier flushes L1 -> __ldg re-missed
// every iteration; SMEM copy removes all post-barrier constant loads).
__global__ void __cluster_dims__(C4_NCTAS, 1, 1) __launch_bounds__(SCAN_THREADS, 1)
scan12_kernel(const float* __restrict__ gammas,
              const float* __restrict__ betas,
              float* __restrict__ hout) {
    extern __shared__ __align__(16) float sm[];
    float* Wsm   = sm;                         // 192*65*4 = 49920 floats
    float* s_hT  = Wsm + R4 * WROW4_F4 * 4;    // 528
    float* s_hp  = s_hT + 528;                 // 768*3 = 2304
    float* s_xpa = s_hp + 2304;                // 2*2*768 = 3072
    float* c_g1  = s_xpa + 3072;               // 768
    float* c_b1  = c_g1 + H3;                  // 768
    float* s_lnA = c_b1 + H3;                  // 24*4 = 96
    float* s_stat= s_lnA + 96;                 // 4 (2 b x mu,rstd)
    int*   s_lb  = (int*)(s_stat + 4);         // 4 (2 par x 2 b)
    int*   s_off = s_lb + 4;                   // 2
    int*   s_ns  = s_off + 2;                  // 2

    const int t    = threadIdx.x;
    const int rank = blockIdx.x & (C4_NCTAS - 1);
    const int clu  = blockIdx.x >> 2;
    const int b0   = clu * NB4;
    const int lane = t & 31, wid = t >> 5;

    // ---- weight slice (rows 192*rank..+191 of U^T), 65-f4 padded rows ----
    {
        const float4* src = (const float4*)(g_Ut + (size_t)(R4 * rank) * HDIM);
        float4* dst = (float4*)Wsm;
        for (int i = t; i < R4 * 64; i += SCAN_THREADS) {
            int row = i >> 6, c4 = i & 63;
            dst[row * WROW4_F4 + c4] = src[(size_t)row * 64 + c4];
        }
    }
    for (int i = t; i < H3; i += SCAN_THREADS) {
        c_g1[i] = gammas[H3 + i];
        c_b1[i] = betas[H3 + i];
    }
    for (int i = t; i < 528; i += SCAN_THREADS) s_hT[i] = 0.0f;

    int maxit = 0;
#pragma unroll
    for (int i = 0; i < NB4; i++) {
        int n = g_nsteps[b0 + i];
        maxit = (n > maxit) ? n : maxit;
    }
    if (t < NB4) {
        s_lb[t]  = g_steplist[(b0 + t) * SL_STRIDE];
        s_off[t] = g_off[b0 + t];
        s_ns[t]  = g_nsteps[b0 + t];
    }
    __syncthreads();

    // prologue: xp(it=0) for 2 batches (384 f4) — already normalized + biased
    if (t < 384) {
        int bb = t / 192, c4 = t - 192 * bb;
        if (s_ns[bb] > 0)
            ((float4*)s_xpa)[t] =
                *((const float4*)g_xpc + (size_t)s_off[bb] * 192 + c4);
    }
    __syncthreads();

    // matvec mapping: thread = (row r_, K-quarter kq)
    const int r_ = t >> 2, kq = t & 3;
    const float4* wf = (const float4*)Wsm + r_ * WROW4_F4 + kq * 16;
    const float4* ht = (const float4*)s_hT + kq * 33;
    float* gbase = g_hp + (size_t)clu * (2 * CLUBUF4);

    for (int it = 0; it < maxit; ++it) {
        const int par = it & 1, nxt = par ^ 1;
        float* gout = gbase + par * CLUBUF4;

        // ================ phase A ================
        float4 pf0, pf1, pf2;
        if (t < 768) {
            float d0 = 0.f, d1 = 0.f;
#pragma unroll
            for (int i = 0; i < 16; i++) {
                float4 w  = wf[i];
                float4 h0 = ht[i * 2 + 0];   // [h(k)b0,h(k)b1,h(k+1)b0,h(k+1)b1]
                float4 h1 = ht[i * 2 + 1];
                d0 += w.x * h0.x + w.y * h0.z;
                d1 += w.x * h0.y + w.y * h0.w;
                d0 += w.z * h1.x + w.w * h1.z;
                d1 += w.z * h1.y + w.w * h1.w;
            }
            d0 += __shfl_xor_sync(0xffffffffu, d0, 1);
            d1 += __shfl_xor_sync(0xffffffffu, d1, 1);
            d0 += __shfl_xor_sync(0xffffffffu, d0, 2);
            d1 += __shfl_xor_sync(0xffffffffu, d1, 2);
            if (kq == 0)
                ((float2*)gout)[rank * (G4_REC / 2) + r_] = make_float2(d0, d1);
            float q0 = d0 * d0, q1 = d1 * d1;
#pragma unroll
            for (int m = 4; m <= 16; m <<= 1) {
                d0 += __shfl_xor_sync(0xffffffffu, d0, m);
                d1 += __shfl_xor_sync(0xffffffffu, d1, m);
                q0 += __shfl_xor_sync(0xffffffffu, q0, m);
                q1 += __shfl_xor_sync(0xffffffffu, q1, m);
            }
            if (lane == 0) {
                s_lnA[wid * 4 + 0] = d0; s_lnA[wid * 4 + 1] = d1;
                s_lnA[wid * 4 + 2] = q0; s_lnA[wid * 4 + 3] = q1;
            }
        } else {
            // helpers: next step indices + prefetch compacted xp(it+1)
            int u = t - 768;
            if (u < NB4) s_lb[nxt * NB4 + u] = g_steplist[(b0 + u) * SL_STRIDE + it + 1];
            const float4* xpf4 = (const float4*)g_xpc;
#pragma unroll
            for (int j = 0; j < 3; j++) {
                int idx = u + 128 * j;        // 0..383
                int bb = idx / 192, c4 = idx - 192 * bb;
                float4 vv = make_float4(0.f, 0.f, 0.f, 0.f);
                if (it + 1 < s_ns[bb])
                    vv = xpf4[(size_t)(s_off[bb] + it + 1) * 192 + c4];
                if (j == 0) pf0 = vv; else if (j == 1) pf1 = vv; else pf2 = vv;
            }
        }
        __syncthreads();
        if (t < 4) {
            float acc = 0.f;
#pragma unroll
            for (int w = 0; w < 24; w++) acc += s_lnA[w * 4 + t];
            gout[rank * G4_REC + 384 + t] = acc;   // [Sd0, Sd1, Sq0, Sq1]
        }

        asm volatile("barrier.cluster.arrive.aligned;" ::: "memory");
        asm volatile("barrier.cluster.wait.aligned;" ::: "memory");

        // ============ gather phase ============
        if (t < 768) {
            int rank_r = t / R4, wrow_r = t - R4 * rank_r;
            float2 v = __ldcv((const float2*)gout + rank_r * (G4_REC / 2) + wrow_r);
            s_hp[t * 3]     = v.x;
            s_hp[t * 3 + 1] = v.y;
            if (t < 2) {   // hp LN stats for batch t
                float S = 0.f, Q = 0.f;
#pragma unroll
                for (int rr = 0; rr < 4; rr++) {
                    S += __ldcv(gout + rr * G4_REC + 384 + t);
                    Q += __ldcv(gout + rr * G4_REC + 386 + t);
                }
                float mu  = S * (1.0f / 768.0f);
                float var = Q * (1.0f / 768.0f) - mu * mu;
                s_stat[t * 2]     = mu;
                s_stat[t * 2 + 1] = rsqrtf(var + 1e-5f);
            }
        } else {
            int u = t - 768;
            float4* xd = (float4*)(s_xpa + nxt * (NB4 * H3));
            xd[u + 0]   = pf0;
            xd[u + 128] = pf1;
            xd[u + 256] = pf2;
        }
        __syncthreads();

        // ============ gates (t<512; all operands SMEM/register) ===============
        if (t < 512) {
            int bb = t >> 8, col = t & 255;
            int lb = s_lb[par * NB4 + bb];
            if (lb >= 0) {
                float mu = s_stat[bb * 2], rs = s_stat[bb * 2 + 1];
                const float* xr = s_xpa + par * (NB4 * H3) + bb * H3;
                float hp0 = (s_hp[col * 3 + bb]         - mu) * rs * c_g1[col]       + c_b1[col];
                float hp1 = (s_hp[(col + 256) * 3 + bb] - mu) * rs * c_g1[col + 256] + c_b1[col + 256];
                float hp2 = (s_hp[(col + 512) * 3 + bb] - mu) * rs * c_g1[col + 512] + c_b1[col + 512];
                float r  = fsig(xr[col]       + hp0);
                float z  = fsig(xr[col + 256] + hp1);
                float hh = ftanhf(xr[col + 512] + r * hp2);
                float hold = s_hT[HT2_FLT(col, bb)];
                float ho = z * hold + (1.0f - z) * hh;
                s_hT[HT2_FLT(col, bb)] = ho;
                if (rank == bb)
                    hout[((size_t)lb * BATCH + b0 + bb) * HDIM + col] = ho;
            }
        }
        __syncthreads();   // s_hT / s_lb / s_xpa stable for next iter
    }
}

// --------------------------------- launcher ----------------------------------
extern "C" void kernel_launch(void* const* d_in, const int* in_sizes, int n_in,
                              void* d_out, int out_size) {
    const float* x     = (const float*)d_in[0];
    const unsigned char* mask = (const unsigned char*)d_in[1];
    const float* W_emb = (const float*)d_in[2];
    const float* b_emb = (const float*)d_in[3];
    const float* W     = (const float*)d_in[4];
    const float* U     = (const float*)d_in[5];
    const float* bgate = (const float*)d_in[6];
    const float* Wa1   = (const float*)d_in[7];
    const float* Ua1   = (const float*)d_in[8];
    const float* ba1   = (const float*)d_in[9];
    const float* Wa2   = (const float*)d_in[10];
    const float* ba2   = (const float*)d_in[11];
    const float* gammas = (const float*)d_in[12];
    const float* betas  = (const float*)d_in[13];
    float* out = (float*)d_out;

    float *h0, *h1, *xpc, *xa;
    int *srcI;
    cudaGetSymbolAddress((void**)&h0, g_h0);
    cudaGetSymbolAddress((void**)&h1, g_h1);
    cudaGetSymbolAddress((void**)&xpc, g_xpc);
    cudaGetSymbolAddress((void**)&xa, g_xa);
    cudaGetSymbolAddress((void**)&srcI, g_srcI);

    const int scan_smem =
        (R4 * WROW4_F4 * 4 + 528 + 2304 + 3072 + 2 * H3 + 96 + 4 + 4 + 2 + 2) * 4;
    static int attr_done = 0;
    if (!attr_done) {
        cudaFuncSetAttribute(scan12_kernel, cudaFuncAttributeMaxDynamicSharedMemorySize, scan_smem);
        attr_done = 1;
    }

    prep_fused<<<H3 + 1, HDIM>>>(U, mask);
    sgemm_kernel<1><<<dim3(HDIM / 64, NROWS / 64), 256>>>(x, W_emb, b_emb, h0, HDIM);

    for (int d = 0; d < DEPTH; d++) {
        float* hin  = (d & 1) ? h1 : h0;
        float* hout = (d & 1) ? h0 : h1;
        sgemm_kernel<3><<<dim3(H3 / 64, NROWS / 64), 256>>>(hin, W, nullptr, xpc, H3);
        lnx_kernel<<<NROWS, 256>>>(xpc, gammas, betas, bgate);
        scan12_kernel<<<NCLU4 * C4_NCTAS, SCAN_THREADS, scan_smem>>>(
            gammas, betas, hout);
        const int* sI = (d == 0) ? nullptr : (srcI + ((d - 1) & 1) * NROWS);
        gemm_head<<<dim3(ADIM / 64, NROWS / 64), 256>>>(hin, hout, sI, Wa1, Ua1, xa);
        head_kernel<<<NROWS, 128>>>(d, xa, ba1, Wa2, ba2, hout, out, out_size);
        if (d < DEPTH - 1) plan_kernel<<<1, 1024>>>((d + 1) & 1);
    }
}